// round 8
// baseline (speedup 1.0000x reference)
#include <cuda_runtime.h>
#include <cuda_bf16.h>
#include <cstdint>

#define FRONT 3072
#define EMBED 768
#define TOKENS 16384

// ---------------- device scratch (no dynamic alloc allowed) ----------------
__device__ __nv_bfloat16 g_W1hi[EMBED * FRONT];
__device__ __nv_bfloat16 g_W1lo[EMBED * FRONT];
__device__ __nv_bfloat16 g_W2hi[EMBED * EMBED];
__device__ __nv_bfloat16 g_W2lo[EMBED * EMBED];
__device__ __nv_bfloat16 g_Ahi[(size_t)TOKENS * FRONT];   // gathered, split embed
__device__ __nv_bfloat16 g_Alo[(size_t)TOKENS * FRONT];
__device__ __nv_bfloat16 g_Yhi[(size_t)TOKENS * EMBED];   // GELU(h1), split
__device__ __nv_bfloat16 g_Ylo[(size_t)TOKENS * EMBED];

// ---------------- tiling ----------------
constexpr int BM = 128;
constexpr int BN = 128;
constexpr int BK = 32;              // bf16 K columns per stage (2 k16 steps)
constexpr int THREADS = 256;
constexpr int STAGES = 2;

// 80-byte pitch = 5 x 16B units (odd) -> any 8 consecutive rows at a fixed 16B
// chunk column hit 8 distinct bank groups: ldmatrix conflict-free, NO swizzle.
constexpr int ROWB  = 80;
constexpr int MAT   = 128 * ROWB;          // 10240 B
constexpr int STAGE = 4 * MAT;             // Ahi, Alo, Bhi, Blo = 40960 B
constexpr int SMEM_TOTAL = STAGES * STAGE; // 81920 B -> 2 CTAs/SM
constexpr int OFF_A_HI = 0;
constexpr int OFF_A_LO = MAT;
constexpr int OFF_B_HI = 2 * MAT;
constexpr int OFF_B_LO = 3 * MAT;

// ---------------- PTX helpers (plain compute_103-legal) ----------------
__device__ __forceinline__ uint32_t smem_u32(const void* p) {
    uint32_t a;
    asm("{ .reg .u64 t; cvta.to.shared.u64 t, %1; cvt.u32.u64 %0, t; }" : "=r"(a) : "l"(p));
    return a;
}
__device__ __forceinline__ void cp16(uint32_t s, const void* g) {
    asm volatile("cp.async.cg.shared.global [%0], [%1], 16;" :: "r"(s), "l"(g));
}
__device__ __forceinline__ void cp_commit() {
    asm volatile("cp.async.commit_group;");
}
__device__ __forceinline__ void ldm4(uint32_t r[4], uint32_t a) {
    asm volatile("ldmatrix.sync.aligned.m8n8.x4.shared.b16 {%0,%1,%2,%3}, [%4];"
                 : "=r"(r[0]), "=r"(r[1]), "=r"(r[2]), "=r"(r[3]) : "r"(a));
}
__device__ __forceinline__ void mma16816(float c[4], const uint32_t a[4],
                                         uint32_t b0, uint32_t b1) {
    asm volatile(
        "mma.sync.aligned.m16n8k16.row.col.f32.bf16.bf16.f32 "
        "{%0,%1,%2,%3}, {%4,%5,%6,%7}, {%8,%9}, {%0,%1,%2,%3};"
        : "+f"(c[0]), "+f"(c[1]), "+f"(c[2]), "+f"(c[3])
        : "r"(a[0]), "r"(a[1]), "r"(a[2]), "r"(a[3]), "r"(b0), "r"(b1));
}

__device__ __forceinline__ void split2(float x, float y, uint32_t& hi, uint32_t& lo) {
    __nv_bfloat162 h = __floats2bfloat162_rn(x, y);
    __nv_bfloat162 l = __floats2bfloat162_rn(x - __low2float(h), y - __high2float(h));
    hi = *(uint32_t*)&h;
    lo = *(uint32_t*)&l;
}

// ---------------- prep: weight split fp32 -> bf16 hi/lo ----------------
__global__ void convert_weights(const float* __restrict__ W1, const float* __restrict__ W2) {
    int i = blockIdx.x * blockDim.x + threadIdx.x;
    if (i < EMBED * FRONT) {
        float x = W1[i];
        __nv_bfloat16 h = __float2bfloat16(x);
        g_W1hi[i] = h;
        g_W1lo[i] = __float2bfloat16(x - __bfloat162float(h));
    }
    if (i < EMBED * EMBED) {
        float x = W2[i];
        __nv_bfloat16 h = __float2bfloat16(x);
        g_W2hi[i] = h;
        g_W2lo[i] = __float2bfloat16(x - __bfloat162float(h));
    }
}

// ---------------- prep: gather + split embedding rows ----------------
__global__ void __launch_bounds__(256, 4)
gather_split(const float* __restrict__ tok, const int* __restrict__ idxs) {
    const int row = blockIdx.x;
    const float4* src = (const float4*)(tok + (size_t)idxs[row] * FRONT);
    uint2* hi = (uint2*)(g_Ahi + (size_t)row * FRONT);
    uint2* lo = (uint2*)(g_Alo + (size_t)row * FRONT);
#pragma unroll
    for (int t = 0; t < FRONT / 4 / 256; ++t) {
        int i = t * 256 + threadIdx.x;
        float4 v = src[i];
        uint2 hv, lv;
        split2(v.x, v.y, hv.x, lv.x);
        split2(v.z, v.w, hv.y, lv.y);
        hi[i] = hv;
        lo[i] = lv;
    }
}

// ---------------- pure split-bf16 mma.sync GEMM, 2-stage BK=32 ----------------
// acc = sum_k A[m,k]*B[n,k]   (AhBh + AhBl + AlBh)
// MODE 0: out fp32 = acc + bias
// MODE 1: v = gelu(acc + bias); write split bf16 to outHi/outLo
template <int MODE>
__global__ void __launch_bounds__(THREADS, 2)
gemm_mma(const __nv_bfloat16* __restrict__ Ahi,
         const __nv_bfloat16* __restrict__ Alo,
         const __nv_bfloat16* __restrict__ Bhi,
         const __nv_bfloat16* __restrict__ Blo,
         const float* __restrict__ bias,
         float* __restrict__ out,
         __nv_bfloat16* __restrict__ outHi,
         __nv_bfloat16* __restrict__ outLo,
         int K) {
    extern __shared__ char sm[];
    const uint32_t sb = smem_u32(sm);

    const int tid = threadIdx.x;
    const int wid = tid >> 5;
    const int l   = tid & 31;
    const int m0  = blockIdx.y * BM;
    const int n0  = blockIdx.x * BN;
    const int wm0 = (wid >> 2) * 64;
    const int wn0 = (wid & 3) * 32;

    // ---- stage loader: tid>>6 selects matrix; (tid&63) covers 2 rows x 4 chunks ----
    const int lmat = tid >> 6;            // 0=Ahi 1=Alo 2=Bhi 3=Blo
    const int lrow = (tid & 63) * 2;      // rows lrow, lrow+1
    const __nv_bfloat16* gsel =
        (lmat == 0) ? Ahi + (size_t)(m0 + lrow) * (size_t)K :
        (lmat == 1) ? Alo + (size_t)(m0 + lrow) * (size_t)K :
        (lmat == 2) ? Bhi + (size_t)(n0 + lrow) * (size_t)K :
                      Blo + (size_t)(n0 + lrow) * (size_t)K;
    const uint32_t sm_mat = (uint32_t)lmat * MAT + (uint32_t)lrow * ROWB;

    auto load_stage = [&](int slot, int c) {
        const uint32_t d = sb + (uint32_t)slot * STAGE + sm_mat;
        const __nv_bfloat16* g = gsel + (size_t)c * BK;
#pragma unroll
        for (int r = 0; r < 2; ++r)
#pragma unroll
            for (int q = 0; q < 4; ++q)
                cp16(d + r * ROWB + q * 16u, g + (size_t)r * K + q * 8);
    };

    float acc[4][4][4];
#pragma unroll
    for (int i = 0; i < 4; ++i)
#pragma unroll
        for (int j = 0; j < 4; ++j)
#pragma unroll
            for (int k = 0; k < 4; ++k) acc[i][j][k] = 0.0f;

    const int r15  = l & 15;
    const int half = l >> 4;

    auto compute = [&](uint32_t stageb) {
#pragma unroll
        for (int s = 0; s < 2; ++s) {
            const uint32_t koff = (uint32_t)(s * 2 + half) * 16u;
            uint32_t Ah[4][4], Al[4][4], Bh[2][4], Bl[2][4];
#pragma unroll
            for (int i = 0; i < 4; ++i) {
                uint32_t ad = stageb + (uint32_t)(wm0 + i * 16 + r15) * ROWB + koff;
                ldm4(Ah[i], ad + OFF_A_HI);
                ldm4(Al[i], ad + OFF_A_LO);
            }
#pragma unroll
            for (int p = 0; p < 2; ++p) {
                uint32_t bd = stageb + (uint32_t)(wn0 + p * 16 + r15) * ROWB + koff;
                ldm4(Bh[p], bd + OFF_B_HI);
                ldm4(Bl[p], bd + OFF_B_LO);
            }
            // term-major: 16 independent MMAs per term
#pragma unroll
            for (int i = 0; i < 4; ++i)
#pragma unroll
                for (int j = 0; j < 4; ++j) {
                    int p = j >> 1, t = j & 1;
                    mma16816(acc[i][j], Ah[i], Bh[p][t], Bh[p][t + 2]);
                }
#pragma unroll
            for (int i = 0; i < 4; ++i)
#pragma unroll
                for (int j = 0; j < 4; ++j) {
                    int p = j >> 1, t = j & 1;
                    mma16816(acc[i][j], Ah[i], Bl[p][t], Bl[p][t + 2]);
                }
#pragma unroll
            for (int i = 0; i < 4; ++i)
#pragma unroll
                for (int j = 0; j < 4; ++j) {
                    int p = j >> 1, t = j & 1;
                    mma16816(acc[i][j], Al[i], Bh[p][t], Bh[p][t + 2]);
                }
        }
    };

    const int nch = K / BK;

    // ---- prologue ----
    load_stage(0, 0);
    cp_commit();

    // ---- mainloop: 2-stage ----
#pragma unroll 1
    for (int c = 0; c < nch; ++c) {
        // all warps done computing chunk c-1 (slot (c-1)&1 == (c+1)&1) before overwrite
        __syncthreads();
        if (c + 1 < nch) load_stage((c + 1) & 1, c + 1);
        cp_commit();
        // chunk c's group complete (1 group left in flight: c+1)
        asm volatile("cp.async.wait_group 1;");
        __syncthreads();   // block-wide visibility of stage c
        compute(sb + (uint32_t)(c & 1) * STAGE);
    }

    // ---- epilogue ----
    const int er = l >> 2;
    const int ec = (l & 3) * 2;
#pragma unroll
    for (int i = 0; i < 4; ++i)
#pragma unroll
        for (int j = 0; j < 4; ++j) {
            int n = n0 + wn0 + j * 8 + ec;
            float bb0 = bias[n], bb1 = bias[n + 1];
#pragma unroll
            for (int h = 0; h < 2; ++h) {
                int m = m0 + wm0 + i * 16 + er + h * 8;
                float v0 = acc[i][j][2 * h]     + bb0;
                float v1 = acc[i][j][2 * h + 1] + bb1;
                if (MODE == 1) {
                    v0 = 0.5f * v0 * (1.0f + erff(v0 * 0.70710678118654752f));
                    v1 = 0.5f * v1 * (1.0f + erff(v1 * 0.70710678118654752f));
                    uint32_t hv, lv;
                    split2(v0, v1, hv, lv);
                    *(uint32_t*)(outHi + (size_t)m * EMBED + n) = hv;
                    *(uint32_t*)(outLo + (size_t)m * EMBED + n) = lv;
                } else {
                    float2 o; o.x = v0; o.y = v1;
                    *(float2*)(out + (size_t)m * EMBED + n) = o;
                }
            }
        }
}

// ---------------- harness entry ----------------
extern "C" void kernel_launch(void* const* d_in, const int* in_sizes, int n_in,
                              void* d_out, int out_size) {
    const int*   idxs = (const int*)d_in[0];
    const float* tok  = (const float*)d_in[1];
    const float* W1   = (const float*)d_in[2];
    const float* b1   = (const float*)d_in[3];
    const float* W2   = (const float*)d_in[4];
    const float* b2   = (const float*)d_in[5];
    float* out = (float*)d_out;

    void *w1h, *w1l, *w2h, *w2l, *ah, *al, *yh, *yl;
    cudaGetSymbolAddress(&w1h, g_W1hi);
    cudaGetSymbolAddress(&w1l, g_W1lo);
    cudaGetSymbolAddress(&w2h, g_W2hi);
    cudaGetSymbolAddress(&w2l, g_W2lo);
    cudaGetSymbolAddress(&ah,  g_Ahi);
    cudaGetSymbolAddress(&al,  g_Alo);
    cudaGetSymbolAddress(&yh,  g_Yhi);
    cudaGetSymbolAddress(&yl,  g_Ylo);

    cudaFuncSetAttribute(gemm_mma<1>,
                         cudaFuncAttributeMaxDynamicSharedMemorySize, SMEM_TOTAL);
    cudaFuncSetAttribute(gemm_mma<0>,
                         cudaFuncAttributeMaxDynamicSharedMemorySize, SMEM_TOTAL);

    const int nW = EMBED * FRONT;
    convert_weights<<<(nW + 255) / 256, 256>>>(W1, W2);
    gather_split<<<TOKENS, 256>>>(tok, idxs);

    // GEMM1: A(split embed) @ W1^T + b1, GELU -> Y split bf16
    gemm_mma<1><<<dim3(EMBED / BN, TOKENS / BM), THREADS, SMEM_TOTAL>>>(
        (const __nv_bfloat16*)ah, (const __nv_bfloat16*)al,
        (const __nv_bfloat16*)w1h, (const __nv_bfloat16*)w1l, b1,
        nullptr, (__nv_bfloat16*)yh, (__nv_bfloat16*)yl, FRONT);

    // GEMM2: Y @ W2^T + b2 -> out fp32
    gemm_mma<0><<<dim3(EMBED / BN, TOKENS / BM), THREADS, SMEM_TOTAL>>>(
        (const __nv_bfloat16*)yh, (const __nv_bfloat16*)yl,
        (const __nv_bfloat16*)w2h, (const __nv_bfloat16*)w2l, b2,
        out, nullptr, nullptr, EMBED);
}

// round 9
// speedup vs baseline: 1.1870x; 1.1870x over previous
#include <cuda_runtime.h>
#include <cuda_bf16.h>
#include <cstdint>

#define FRONT 3072
#define EMBED 768
#define TOKENS 16384

// ---------------- device scratch (no dynamic alloc allowed) ----------------
__device__ __nv_bfloat16 g_W1hi[EMBED * FRONT];
__device__ __nv_bfloat16 g_W1lo[EMBED * FRONT];
__device__ __nv_bfloat16 g_W2hi[EMBED * EMBED];
__device__ __nv_bfloat16 g_W2lo[EMBED * EMBED];
__device__ __nv_bfloat16 g_Ahi[(size_t)TOKENS * FRONT];   // gathered, split embed
__device__ __nv_bfloat16 g_Alo[(size_t)TOKENS * FRONT];
__device__ __nv_bfloat16 g_Yhi[(size_t)TOKENS * EMBED];   // GELU(h1), split
__device__ __nv_bfloat16 g_Ylo[(size_t)TOKENS * EMBED];

// ---------------- tiling ----------------
constexpr int BM = 128;
constexpr int BN = 128;
constexpr int BK = 32;              // bf16 K columns per stage (2 k16 steps)
constexpr int THREADS = 256;
constexpr int STAGES = 3;

// 80-byte pitch = 5 x 16B units (odd) -> any 8 consecutive rows at a fixed 16B
// chunk column hit 8 distinct bank groups: ldmatrix conflict-free, NO swizzle.
constexpr int ROWB  = 80;
constexpr int MAT   = 128 * ROWB;          // 10240 B
constexpr int STAGE = 4 * MAT;             // Ahi, Alo, Bhi, Blo = 40960 B
constexpr int SMEM_TOTAL = STAGES * STAGE; // 122880 B -> 1 CTA/SM
constexpr int OFF_A_HI = 0;
constexpr int OFF_A_LO = MAT;
constexpr int OFF_B_HI = 2 * MAT;
constexpr int OFF_B_LO = 3 * MAT;

// ---------------- PTX helpers (plain compute_103-legal) ----------------
__device__ __forceinline__ uint32_t smem_u32(const void* p) {
    uint32_t a;
    asm("{ .reg .u64 t; cvta.to.shared.u64 t, %1; cvt.u32.u64 %0, t; }" : "=r"(a) : "l"(p));
    return a;
}
__device__ __forceinline__ void cp16(uint32_t s, const void* g) {
    asm volatile("cp.async.cg.shared.global [%0], [%1], 16;" :: "r"(s), "l"(g));
}
__device__ __forceinline__ void cp_commit() {
    asm volatile("cp.async.commit_group;");
}
__device__ __forceinline__ void ldm4(uint32_t r[4], uint32_t a) {
    asm volatile("ldmatrix.sync.aligned.m8n8.x4.shared.b16 {%0,%1,%2,%3}, [%4];"
                 : "=r"(r[0]), "=r"(r[1]), "=r"(r[2]), "=r"(r[3]) : "r"(a));
}
__device__ __forceinline__ void mma16816(float c[4], const uint32_t a[4],
                                         uint32_t b0, uint32_t b1) {
    asm volatile(
        "mma.sync.aligned.m16n8k16.row.col.f32.bf16.bf16.f32 "
        "{%0,%1,%2,%3}, {%4,%5,%6,%7}, {%8,%9}, {%0,%1,%2,%3};"
        : "+f"(c[0]), "+f"(c[1]), "+f"(c[2]), "+f"(c[3])
        : "r"(a[0]), "r"(a[1]), "r"(a[2]), "r"(a[3]), "r"(b0), "r"(b1));
}

__device__ __forceinline__ void split2(float x, float y, uint32_t& hi, uint32_t& lo) {
    __nv_bfloat162 h = __floats2bfloat162_rn(x, y);
    __nv_bfloat162 l = __floats2bfloat162_rn(x - __low2float(h), y - __high2float(h));
    hi = *(uint32_t*)&h;
    lo = *(uint32_t*)&l;
}

// ---------------- prep: weight split fp32 -> bf16 hi/lo ----------------
__global__ void convert_weights(const float* __restrict__ W1, const float* __restrict__ W2) {
    int i = blockIdx.x * blockDim.x + threadIdx.x;
    if (i < EMBED * FRONT) {
        float x = W1[i];
        __nv_bfloat16 h = __float2bfloat16(x);
        g_W1hi[i] = h;
        g_W1lo[i] = __float2bfloat16(x - __bfloat162float(h));
    }
    if (i < EMBED * EMBED) {
        float x = W2[i];
        __nv_bfloat16 h = __float2bfloat16(x);
        g_W2hi[i] = h;
        g_W2lo[i] = __float2bfloat16(x - __bfloat162float(h));
    }
}

// ---------------- prep: gather + split embedding rows ----------------
__global__ void __launch_bounds__(256, 4)
gather_split(const float* __restrict__ tok, const int* __restrict__ idxs) {
    const int row = blockIdx.x;
    const float4* src = (const float4*)(tok + (size_t)idxs[row] * FRONT);
    uint2* hi = (uint2*)(g_Ahi + (size_t)row * FRONT);
    uint2* lo = (uint2*)(g_Alo + (size_t)row * FRONT);
#pragma unroll
    for (int t = 0; t < FRONT / 4 / 256; ++t) {
        int i = t * 256 + threadIdx.x;
        float4 v = src[i];
        uint2 hv, lv;
        split2(v.x, v.y, hv.x, lv.x);
        split2(v.z, v.w, hv.y, lv.y);
        hi[i] = hv;
        lo[i] = lv;
    }
}

// ---------------- fragment set for one k16-step ----------------
struct Frags {
    uint32_t Ah[4][4], Al[4][4], Bh[2][4], Bl[2][4];
};

// ---------------- pure split-bf16 mma.sync GEMM ----------------
// Software-pipelined: fragment ping-pong across k-steps, 3-stage cp.async ring.
// acc = sum_k A[m,k]*B[n,k]   (AhBh + AhBl + AlBh)
// MODE 0: out fp32 = acc + bias
// MODE 1: v = gelu(acc + bias); write split bf16 to outHi/outLo
template <int MODE>
__global__ void __launch_bounds__(THREADS, 1)
gemm_mma(const __nv_bfloat16* __restrict__ Ahi,
         const __nv_bfloat16* __restrict__ Alo,
         const __nv_bfloat16* __restrict__ Bhi,
         const __nv_bfloat16* __restrict__ Blo,
         const float* __restrict__ bias,
         float* __restrict__ out,
         __nv_bfloat16* __restrict__ outHi,
         __nv_bfloat16* __restrict__ outLo,
         int K) {
    extern __shared__ char sm[];
    const uint32_t sb = smem_u32(sm);

    const int tid = threadIdx.x;
    const int wid = tid >> 5;
    const int l   = tid & 31;
    const int m0  = blockIdx.y * BM;
    const int n0  = blockIdx.x * BN;
    const int wm0 = (wid >> 2) * 64;
    const int wn0 = (wid & 3) * 32;

    // ---- stage loader: tid>>6 selects matrix; (tid&63) covers 2 rows x 4 chunks ----
    const int lmat = tid >> 6;            // 0=Ahi 1=Alo 2=Bhi 3=Blo
    const int lrow = (tid & 63) * 2;      // rows lrow, lrow+1
    const __nv_bfloat16* gsel =
        (lmat == 0) ? Ahi + (size_t)(m0 + lrow) * (size_t)K :
        (lmat == 1) ? Alo + (size_t)(m0 + lrow) * (size_t)K :
        (lmat == 2) ? Bhi + (size_t)(n0 + lrow) * (size_t)K :
                      Blo + (size_t)(n0 + lrow) * (size_t)K;
    const uint32_t sm_mat = (uint32_t)lmat * MAT + (uint32_t)lrow * ROWB;

    auto load_stage = [&](int slot, int c) {
        const uint32_t d = sb + (uint32_t)slot * STAGE + sm_mat;
        const __nv_bfloat16* g = gsel + (size_t)c * BK;
#pragma unroll
        for (int r = 0; r < 2; ++r)
#pragma unroll
            for (int q = 0; q < 4; ++q)
                cp16(d + r * ROWB + q * 16u, g + (size_t)r * K + q * 8);
    };

    const int r15  = l & 15;
    const int half = l >> 4;

    // koff for k16-step s: chunks (s*2 + half)
    auto load_frags = [&](Frags& f, uint32_t stageb, int step) {
        const uint32_t koff = (uint32_t)(step * 2 + half) * 16u;
#pragma unroll
        for (int i = 0; i < 4; ++i) {
            uint32_t ad = stageb + (uint32_t)(wm0 + i * 16 + r15) * ROWB + koff;
            ldm4(f.Ah[i], ad + OFF_A_HI);
            ldm4(f.Al[i], ad + OFF_A_LO);
        }
#pragma unroll
        for (int p = 0; p < 2; ++p) {
            uint32_t bd = stageb + (uint32_t)(wn0 + p * 16 + r15) * ROWB + koff;
            ldm4(f.Bh[p], bd + OFF_B_HI);
            ldm4(f.Bl[p], bd + OFF_B_LO);
        }
    };

    float acc[4][4][4];
#pragma unroll
    for (int i = 0; i < 4; ++i)
#pragma unroll
        for (int j = 0; j < 4; ++j)
#pragma unroll
            for (int k = 0; k < 4; ++k) acc[i][j][k] = 0.0f;

    auto mma_frags = [&](const Frags& f) {
        // term-major: 16 independent MMAs per term -> accumulator reuse distance 16
#pragma unroll
        for (int i = 0; i < 4; ++i)
#pragma unroll
            for (int j = 0; j < 4; ++j) {
                int p = j >> 1, t = j & 1;
                mma16816(acc[i][j], f.Ah[i], f.Bh[p][t], f.Bh[p][t + 2]);
            }
#pragma unroll
        for (int i = 0; i < 4; ++i)
#pragma unroll
            for (int j = 0; j < 4; ++j) {
                int p = j >> 1, t = j & 1;
                mma16816(acc[i][j], f.Ah[i], f.Bl[p][t], f.Bl[p][t + 2]);
            }
#pragma unroll
        for (int i = 0; i < 4; ++i)
#pragma unroll
            for (int j = 0; j < 4; ++j) {
                int p = j >> 1, t = j & 1;
                mma16816(acc[i][j], f.Al[i], f.Bh[p][t], f.Bh[p][t + 2]);
            }
    };

    const int nch = K / BK;   // >= 24, multiple of STAGES not required

    // ---- prologue: fill stages 0,1; prefetch first fragment set ----
    load_stage(0, 0);
    cp_commit();
    load_stage(1, 1);
    cp_commit();
    asm volatile("cp.async.wait_group 1;");   // chunk 0 resident (own groups)
    __syncthreads();                           // block-wide visibility

    Frags f0, f1;
    load_frags(f0, sb, 0);                     // chunk 0, step 0

    // ---- mainloop ----
    int slot = 0;                              // stage slot of chunk c
#pragma unroll 1
    for (int c = 0; c < nch; ++c) {
        const uint32_t stc = sb + (uint32_t)slot * STAGE;
        const int slot2 = (slot + 2 >= STAGES) ? slot + 2 - STAGES : slot + 2;
        const int slot1 = (slot + 1 >= STAGES) ? slot + 1 - STAGES : slot + 1;

        // prefetch step-1 fragments of this chunk (same stage, already visible)
        load_frags(f1, stc, 1);

        // 48 MMAs on step-0 fragments (loaded last iteration)
        mma_frags(f0);

        // refill ring: chunk c+2 -> slot2 (overwrites chunk c-1's stage; its last
        // reader was load_frags(f1) in iteration c-1, two barriers back)
        if (c + 2 < nch) load_stage(slot2, c + 2);
        cp_commit();                           // always commit: group count stays aligned
        asm volatile("cp.async.wait_group 1;");// all but newest retired -> chunk c+1 done
        __syncthreads();                       // cross-warp visibility of stage c+1

        // prefetch step-0 fragments of chunk c+1
        if (c + 1 < nch) load_frags(f0, sb + (uint32_t)slot1 * STAGE, 0);

        // 48 MMAs on step-1 fragments
        mma_frags(f1);

        slot = slot1;
    }

    // ---- epilogue ----
    const int er = l >> 2;
    const int ec = (l & 3) * 2;
#pragma unroll
    for (int i = 0; i < 4; ++i)
#pragma unroll
        for (int j = 0; j < 4; ++j) {
            int n = n0 + wn0 + j * 8 + ec;
            float bb0 = bias[n], bb1 = bias[n + 1];
#pragma unroll
            for (int h = 0; h < 2; ++h) {
                int m = m0 + wm0 + i * 16 + er + h * 8;
                float v0 = acc[i][j][2 * h]     + bb0;
                float v1 = acc[i][j][2 * h + 1] + bb1;
                if (MODE == 1) {
                    v0 = 0.5f * v0 * (1.0f + erff(v0 * 0.70710678118654752f));
                    v1 = 0.5f * v1 * (1.0f + erff(v1 * 0.70710678118654752f));
                    uint32_t hv, lv;
                    split2(v0, v1, hv, lv);
                    *(uint32_t*)(outHi + (size_t)m * EMBED + n) = hv;
                    *(uint32_t*)(outLo + (size_t)m * EMBED + n) = lv;
                } else {
                    float2 o; o.x = v0; o.y = v1;
                    *(float2*)(out + (size_t)m * EMBED + n) = o;
                }
            }
        }
}

// ---------------- harness entry ----------------
extern "C" void kernel_launch(void* const* d_in, const int* in_sizes, int n_in,
                              void* d_out, int out_size) {
    const int*   idxs = (const int*)d_in[0];
    const float* tok  = (const float*)d_in[1];
    const float* W1   = (const float*)d_in[2];
    const float* b1   = (const float*)d_in[3];
    const float* W2   = (const float*)d_in[4];
    const float* b2   = (const float*)d_in[5];
    float* out = (float*)d_out;

    void *w1h, *w1l, *w2h, *w2l, *ah, *al, *yh, *yl;
    cudaGetSymbolAddress(&w1h, g_W1hi);
    cudaGetSymbolAddress(&w1l, g_W1lo);
    cudaGetSymbolAddress(&w2h, g_W2hi);
    cudaGetSymbolAddress(&w2l, g_W2lo);
    cudaGetSymbolAddress(&ah,  g_Ahi);
    cudaGetSymbolAddress(&al,  g_Alo);
    cudaGetSymbolAddress(&yh,  g_Yhi);
    cudaGetSymbolAddress(&yl,  g_Ylo);

    cudaFuncSetAttribute(gemm_mma<1>,
                         cudaFuncAttributeMaxDynamicSharedMemorySize, SMEM_TOTAL);
    cudaFuncSetAttribute(gemm_mma<0>,
                         cudaFuncAttributeMaxDynamicSharedMemorySize, SMEM_TOTAL);

    const int nW = EMBED * FRONT;
    convert_weights<<<(nW + 255) / 256, 256>>>(W1, W2);
    gather_split<<<TOKENS, 256>>>(tok, idxs);

    // GEMM1: A(split embed) @ W1^T + b1, GELU -> Y split bf16
    gemm_mma<1><<<dim3(EMBED / BN, TOKENS / BM), THREADS, SMEM_TOTAL>>>(
        (const __nv_bfloat16*)ah, (const __nv_bfloat16*)al,
        (const __nv_bfloat16*)w1h, (const __nv_bfloat16*)w1l, b1,
        nullptr, (__nv_bfloat16*)yh, (__nv_bfloat16*)yl, FRONT);

    // GEMM2: Y @ W2^T + b2 -> out fp32
    gemm_mma<0><<<dim3(EMBED / BN, TOKENS / BM), THREADS, SMEM_TOTAL>>>(
        (const __nv_bfloat16*)yh, (const __nv_bfloat16*)yl,
        (const __nv_bfloat16*)w2h, (const __nv_bfloat16*)w2l, b2,
        out, nullptr, nullptr, EMBED);
}

// round 11
// speedup vs baseline: 1.5174x; 1.2783x over previous
#include <cuda_runtime.h>
#include <cuda_fp16.h>
#include <cstdint>

#define FRONT 3072
#define EMBED 768
#define TOKENS 16384

// ---------------- device scratch (no dynamic alloc allowed) ----------------
__device__ __half g_W1h[EMBED * FRONT];                 // fp16 weights (single)
__device__ __half g_W2h[EMBED * EMBED];
__device__ __half g_Ahi[(size_t)TOKENS * FRONT];        // gathered embed, fp16 hi/lo
__device__ __half g_Alo[(size_t)TOKENS * FRONT];
__device__ __half g_Yhi[(size_t)TOKENS * EMBED];        // GELU(h1), fp16 hi/lo
__device__ __half g_Ylo[(size_t)TOKENS * EMBED];

// ---------------- tiling ----------------
constexpr int BM = 128;
constexpr int BN = 128;
constexpr int BK = 32;              // fp16 K columns per stage (2 k16 steps)
constexpr int THREADS = 256;
constexpr int STAGES = 3;

// 80-byte pitch = 5 x 16B units (odd) -> any 8 consecutive rows at a fixed 16B
// chunk column hit 8 distinct bank groups: ldmatrix conflict-free, NO swizzle.
constexpr int ROWB  = 80;
constexpr int MAT   = 128 * ROWB;          // 10240 B
constexpr int STAGE = 3 * MAT;             // Ahi, Alo, B = 30720 B
constexpr int SMEM_TOTAL = STAGES * STAGE; // 92160 B
constexpr int OFF_A_HI = 0;
constexpr int OFF_A_LO = MAT;
constexpr int OFF_B    = 2 * MAT;

// ---------------- PTX helpers (plain compute_103-legal) ----------------
__device__ __forceinline__ uint32_t smem_u32(const void* p) {
    uint32_t a;
    asm("{ .reg .u64 t; cvta.to.shared.u64 t, %1; cvt.u32.u64 %0, t; }" : "=r"(a) : "l"(p));
    return a;
}
__device__ __forceinline__ void cp16(uint32_t s, const void* g) {
    asm volatile("cp.async.cg.shared.global [%0], [%1], 16;" :: "r"(s), "l"(g));
}
__device__ __forceinline__ void cp_commit() {
    asm volatile("cp.async.commit_group;");
}
__device__ __forceinline__ void ldm4(uint32_t r[4], uint32_t a) {
    asm volatile("ldmatrix.sync.aligned.m8n8.x4.shared.b16 {%0,%1,%2,%3}, [%4];"
                 : "=r"(r[0]), "=r"(r[1]), "=r"(r[2]), "=r"(r[3]) : "r"(a));
}
__device__ __forceinline__ void mma16816(float c[4], const uint32_t a[4],
                                         uint32_t b0, uint32_t b1) {
    asm volatile(
        "mma.sync.aligned.m16n8k16.row.col.f32.f16.f16.f32 "
        "{%0,%1,%2,%3}, {%4,%5,%6,%7}, {%8,%9}, {%0,%1,%2,%3};"
        : "+f"(c[0]), "+f"(c[1]), "+f"(c[2]), "+f"(c[3])
        : "r"(a[0]), "r"(a[1]), "r"(a[2]), "r"(a[3]), "r"(b0), "r"(b1));
}

__device__ __forceinline__ void split2h(float x, float y, uint32_t& hi, uint32_t& lo) {
    __half2 h = __floats2half2_rn(x, y);
    __half2 l = __floats2half2_rn(x - __low2float(h), y - __high2float(h));
    hi = *(uint32_t*)&h;
    lo = *(uint32_t*)&l;
}

// ---------------- prep: weights fp32 -> fp16 (single) ----------------
__global__ void convert_weights(const float* __restrict__ W1, const float* __restrict__ W2) {
    int i = blockIdx.x * blockDim.x + threadIdx.x;
    if (i < EMBED * FRONT) g_W1h[i] = __float2half_rn(W1[i]);
    if (i < EMBED * EMBED) g_W2h[i] = __float2half_rn(W2[i]);
}

// ---------------- prep: gather + fp16 hi/lo split of embedding rows ----------------
__global__ void __launch_bounds__(256, 4)
gather_split(const float* __restrict__ tok, const int* __restrict__ idxs) {
    const int row = blockIdx.x;
    const float4* src = (const float4*)(tok + (size_t)idxs[row] * FRONT);
    uint2* hi = (uint2*)(g_Ahi + (size_t)row * FRONT);
    uint2* lo = (uint2*)(g_Alo + (size_t)row * FRONT);
#pragma unroll
    for (int t = 0; t < FRONT / 4 / 256; ++t) {
        int i = t * 256 + threadIdx.x;
        float4 v = src[i];
        uint2 hv, lv;
        split2h(v.x, v.y, hv.x, lv.x);
        split2h(v.z, v.w, hv.y, lv.y);
        hi[i] = hv;
        lo[i] = lv;
    }
}

// ---------------- fragment set for one k16-step ----------------
struct Frags {
    uint32_t Ah[4][4], Al[4][4], B[2][4];
};

// ---------------- 2-term split-fp16 mma.sync GEMM ----------------
// acc = sum_k (Ah+Al)[m,k] * B[n,k]     (fp16, fp32 accum)
// MODE 0: out fp32 = acc + bias
// MODE 1: v = gelu(acc + bias); write split fp16 to outHi/outLo
template <int MODE>
__global__ void __launch_bounds__(THREADS, 1)
gemm_mma(const __half* __restrict__ Ahi,
         const __half* __restrict__ Alo,
         const __half* __restrict__ Bw,
         const float* __restrict__ bias,
         float* __restrict__ out,
         __half* __restrict__ outHi,
         __half* __restrict__ outLo,
         int K) {
    extern __shared__ char sm[];
    const uint32_t sb = smem_u32(sm);

    const int tid = threadIdx.x;
    const int wid = tid >> 5;
    const int l   = tid & 31;
    const int m0  = blockIdx.y * BM;
    const int n0  = blockIdx.x * BN;
    const int wm0 = (wid >> 2) * 64;
    const int wn0 = (wid & 3) * 32;

    // ---- stage loader: thread -> (row = tid&127, 32B half = tid>>7), 3 matrices ----
    const int lrow = tid & 127;
    const int lh   = tid >> 7;       // 0/1
    const __half* gAh = Ahi + (size_t)(m0 + lrow) * (size_t)K + lh * 16;
    const __half* gAl = Alo + (size_t)(m0 + lrow) * (size_t)K + lh * 16;
    const __half* gB  = Bw  + (size_t)(n0 + lrow) * (size_t)K + lh * 16;
    const uint32_t sm_row = (uint32_t)lrow * ROWB + (uint32_t)lh * 32u;

    auto load_stage = [&](int slot, int c) {
        const uint32_t d = sb + (uint32_t)slot * STAGE + sm_row;
        const size_t go = (size_t)c * BK;
        cp16(d + OFF_A_HI,      gAh + go);
        cp16(d + OFF_A_HI + 16, gAh + go + 8);
        cp16(d + OFF_A_LO,      gAl + go);
        cp16(d + OFF_A_LO + 16, gAl + go + 8);
        cp16(d + OFF_B,         gB  + go);
        cp16(d + OFF_B + 16,    gB  + go + 8);
    };

    const int r15  = l & 15;
    const int half = l >> 4;

    // koff for k16-step s: 16B chunk (s*2 + half)
    auto load_frags = [&](Frags& f, uint32_t stageb, int step) {
        const uint32_t koff = (uint32_t)(step * 2 + half) * 16u;
#pragma unroll
        for (int i = 0; i < 4; ++i) {
            uint32_t ad = stageb + (uint32_t)(wm0 + i * 16 + r15) * ROWB + koff;
            ldm4(f.Ah[i], ad + OFF_A_HI);
            ldm4(f.Al[i], ad + OFF_A_LO);
        }
#pragma unroll
        for (int p = 0; p < 2; ++p) {
            uint32_t bd = stageb + (uint32_t)(wn0 + p * 16 + r15) * ROWB + koff;
            ldm4(f.B[p], bd + OFF_B);
        }
    };

    float acc[4][4][4];
#pragma unroll
    for (int i = 0; i < 4; ++i)
#pragma unroll
        for (int j = 0; j < 4; ++j)
#pragma unroll
            for (int k = 0; k < 4; ++k) acc[i][j][k] = 0.0f;

    auto mma_frags = [&](const Frags& f) {
        // term-major: 16 independent MMAs per term -> accumulator reuse distance 16
#pragma unroll
        for (int i = 0; i < 4; ++i)
#pragma unroll
            for (int j = 0; j < 4; ++j) {
                int p = j >> 1, t = j & 1;
                mma16816(acc[i][j], f.Ah[i], f.B[p][t], f.B[p][t + 2]);
            }
#pragma unroll
        for (int i = 0; i < 4; ++i)
#pragma unroll
            for (int j = 0; j < 4; ++j) {
                int p = j >> 1, t = j & 1;
                mma16816(acc[i][j], f.Al[i], f.B[p][t], f.B[p][t + 2]);
            }
    };

    const int nch = K / BK;

    // ---- prologue: fill stages 0,1; prefetch first fragment set ----
    load_stage(0, 0);
    cp_commit();
    load_stage(1, 1);
    cp_commit();
    asm volatile("cp.async.wait_group 1;");   // chunk 0 resident (own groups)
    __syncthreads();                           // block-wide visibility

    Frags f0, f1;
    load_frags(f0, sb, 0);                     // chunk 0, step 0

    // ---- mainloop (R8 schedule, unchanged) ----
    int slot = 0;
#pragma unroll 1
    for (int c = 0; c < nch; ++c) {
        const uint32_t stc = sb + (uint32_t)slot * STAGE;
        const int slot2 = (slot + 2 >= STAGES) ? slot + 2 - STAGES : slot + 2;
        const int slot1 = (slot + 1 >= STAGES) ? slot + 1 - STAGES : slot + 1;

        // prefetch step-1 fragments of this chunk (same stage, already visible)
        load_frags(f1, stc, 1);

        // 32 MMAs on step-0 fragments (loaded last iteration)
        mma_frags(f0);

        // refill ring: chunk c+2 -> slot2
        if (c + 2 < nch) load_stage(slot2, c + 2);
        cp_commit();
        asm volatile("cp.async.wait_group 1;");// all but newest retired -> chunk c+1 done
        __syncthreads();                       // cross-warp visibility of stage c+1

        // prefetch step-0 fragments of chunk c+1
        if (c + 1 < nch) load_frags(f0, sb + (uint32_t)slot1 * STAGE, 0);

        // 32 MMAs on step-1 fragments
        mma_frags(f1);

        slot = slot1;
    }

    // ---- epilogue ----
    const int er = l >> 2;
    const int ec = (l & 3) * 2;
#pragma unroll
    for (int i = 0; i < 4; ++i)
#pragma unroll
        for (int j = 0; j < 4; ++j) {
            int n = n0 + wn0 + j * 8 + ec;
            float bb0 = bias[n], bb1 = bias[n + 1];
#pragma unroll
            for (int h = 0; h < 2; ++h) {
                int m = m0 + wm0 + i * 16 + er + h * 8;
                float v0 = acc[i][j][2 * h]     + bb0;
                float v1 = acc[i][j][2 * h + 1] + bb1;
                if (MODE == 1) {
                    v0 = 0.5f * v0 * (1.0f + erff(v0 * 0.70710678118654752f));
                    v1 = 0.5f * v1 * (1.0f + erff(v1 * 0.70710678118654752f));
                    uint32_t hv, lv;
                    split2h(v0, v1, hv, lv);
                    *(uint32_t*)(outHi + (size_t)m * EMBED + n) = hv;
                    *(uint32_t*)(outLo + (size_t)m * EMBED + n) = lv;
                } else {
                    float2 o; o.x = v0; o.y = v1;
                    *(float2*)(out + (size_t)m * EMBED + n) = o;
                }
            }
        }
}

// ---------------- harness entry ----------------
extern "C" void kernel_launch(void* const* d_in, const int* in_sizes, int n_in,
                              void* d_out, int out_size) {
    const int*   idxs = (const int*)d_in[0];
    const float* tok  = (const float*)d_in[1];
    const float* W1   = (const float*)d_in[2];
    const float* b1   = (const float*)d_in[3];
    const float* W2   = (const float*)d_in[4];
    const float* b2   = (const float*)d_in[5];
    float* out = (float*)d_out;

    void *w1h, *w2h, *ah, *al, *yh, *yl;
    cudaGetSymbolAddress(&w1h, g_W1h);
    cudaGetSymbolAddress(&w2h, g_W2h);
    cudaGetSymbolAddress(&ah,  g_Ahi);
    cudaGetSymbolAddress(&al,  g_Alo);
    cudaGetSymbolAddress(&yh,  g_Yhi);
    cudaGetSymbolAddress(&yl,  g_Ylo);

    cudaFuncSetAttribute(gemm_mma<1>,
                         cudaFuncAttributeMaxDynamicSharedMemorySize, SMEM_TOTAL);
    cudaFuncSetAttribute(gemm_mma<0>,
                         cudaFuncAttributeMaxDynamicSharedMemorySize, SMEM_TOTAL);

    const int nW = EMBED * FRONT;
    convert_weights<<<(nW + 255) / 256, 256>>>(W1, W2);
    gather_split<<<TOKENS, 256>>>(tok, idxs);

    // GEMM1: (Ah+Al) @ W1^T + b1, GELU -> Y split fp16
    gemm_mma<1><<<dim3(EMBED / BN, TOKENS / BM), THREADS, SMEM_TOTAL>>>(
        (const __half*)ah, (const __half*)al, (const __half*)w1h, b1,
        nullptr, (__half*)yh, (__half*)yl, FRONT);

    // GEMM2: (Yh+Yl) @ W2^T + b2 -> out fp32
    gemm_mma<0><<<dim3(EMBED / BN, TOKENS / BM), THREADS, SMEM_TOTAL>>>(
        (const __half*)yh, (const __half*)yl, (const __half*)w2h, b2,
        out, nullptr, nullptr, EMBED);
}

// round 12
// speedup vs baseline: 2.6627x; 1.7548x over previous
#include <cuda_runtime.h>
#include <cuda_fp16.h>
#include <cstdint>

#define FRONT 3072
#define EMBED 768
#define TOKENS 16384

// ---------------- device scratch (no dynamic alloc allowed) ----------------
__device__ __half g_W1h[EMBED * FRONT];                 // fp16 weights
__device__ __half g_W2h[EMBED * EMBED];
__device__ __half g_A[(size_t)TOKENS * FRONT];          // gathered embed, fp16
__device__ __half g_Y[(size_t)TOKENS * EMBED];          // GELU(h1), fp16

// ---------------- tiling ----------------
constexpr int BM = 128;
constexpr int BN = 128;
constexpr int BK = 32;              // fp16 K columns per stage (2 k16 steps)
constexpr int THREADS = 256;
constexpr int STAGES = 3;

// 80-byte pitch = 5 x 16B units (odd) -> any 8 consecutive rows at a fixed 16B
// chunk column hit 8 distinct bank groups: ldmatrix conflict-free, NO swizzle.
constexpr int ROWB  = 80;
constexpr int MAT   = 128 * ROWB;          // 10240 B
constexpr int STAGE = 2 * MAT;             // A, B = 20480 B
constexpr int SMEM_TOTAL = STAGES * STAGE; // 61440 B -> 2 CTAs/SM
constexpr int OFF_A = 0;
constexpr int OFF_B = MAT;

// ---------------- PTX helpers (plain compute_103-legal) ----------------
__device__ __forceinline__ uint32_t smem_u32(const void* p) {
    uint32_t a;
    asm("{ .reg .u64 t; cvta.to.shared.u64 t, %1; cvt.u32.u64 %0, t; }" : "=r"(a) : "l"(p));
    return a;
}
__device__ __forceinline__ void cp16(uint32_t s, const void* g) {
    asm volatile("cp.async.cg.shared.global [%0], [%1], 16;" :: "r"(s), "l"(g));
}
__device__ __forceinline__ void cp_commit() {
    asm volatile("cp.async.commit_group;");
}
__device__ __forceinline__ void ldm4(uint32_t r[4], uint32_t a) {
    asm volatile("ldmatrix.sync.aligned.m8n8.x4.shared.b16 {%0,%1,%2,%3}, [%4];"
                 : "=r"(r[0]), "=r"(r[1]), "=r"(r[2]), "=r"(r[3]) : "r"(a));
}
__device__ __forceinline__ void mma16816(float c[4], const uint32_t a[4],
                                         uint32_t b0, uint32_t b1) {
    asm volatile(
        "mma.sync.aligned.m16n8k16.row.col.f32.f16.f16.f32 "
        "{%0,%1,%2,%3}, {%4,%5,%6,%7}, {%8,%9}, {%0,%1,%2,%3};"
        : "+f"(c[0]), "+f"(c[1]), "+f"(c[2]), "+f"(c[3])
        : "r"(a[0]), "r"(a[1]), "r"(a[2]), "r"(a[3]), "r"(b0), "r"(b1));
}

// ---------------- prep: weights fp32 -> fp16 ----------------
__global__ void convert_weights(const float* __restrict__ W1, const float* __restrict__ W2) {
    int i = blockIdx.x * blockDim.x + threadIdx.x;
    if (i < EMBED * FRONT) g_W1h[i] = __float2half_rn(W1[i]);
    if (i < EMBED * EMBED) g_W2h[i] = __float2half_rn(W2[i]);
}

// ---------------- prep: gather + fp16 convert of embedding rows ----------------
__global__ void __launch_bounds__(256, 4)
gather_fp16(const float* __restrict__ tok, const int* __restrict__ idxs) {
    const int row = blockIdx.x;
    const float4* src = (const float4*)(tok + (size_t)idxs[row] * FRONT);
    uint2* dst = (uint2*)(g_A + (size_t)row * FRONT);
#pragma unroll
    for (int t = 0; t < FRONT / 4 / 256; ++t) {
        int i = t * 256 + threadIdx.x;
        float4 v = src[i];
        __half2 h01 = __floats2half2_rn(v.x, v.y);
        __half2 h23 = __floats2half2_rn(v.z, v.w);
        uint2 o;
        o.x = *(uint32_t*)&h01;
        o.y = *(uint32_t*)&h23;
        dst[i] = o;
    }
}

// ---------------- fragment set for one k16-step ----------------
struct Frags {
    uint32_t A[4][4], B[2][4];
};

// ---------------- single-term fp16 mma.sync GEMM, ping-pong pipelined ----------------
// acc = sum_k A[m,k] * B[n,k]     (fp16 in, fp32 accum)
// MODE 0: out fp32 = acc + bias
// MODE 1: v = gelu(acc + bias); write fp16 to outH
template <int MODE>
__global__ void __launch_bounds__(THREADS, 2)
gemm_mma(const __half* __restrict__ Ax,
         const __half* __restrict__ Bw,
         const float* __restrict__ bias,
         float* __restrict__ out,
         __half* __restrict__ outH,
         int K) {
    extern __shared__ char sm[];
    const uint32_t sb = smem_u32(sm);

    const int tid = threadIdx.x;
    const int wid = tid >> 5;
    const int l   = tid & 31;
    const int m0  = blockIdx.y * BM;
    const int n0  = blockIdx.x * BN;
    const int wm0 = (wid >> 2) * 64;
    const int wn0 = (wid & 3) * 32;

    // ---- stage loader: tid>>7 selects matrix, tid&127 the row; 4 cp16 = 64B row ----
    const int lmat = tid >> 7;            // 0=A, 1=B
    const int lrow = tid & 127;
    const __half* gsrc = (lmat == 0) ? Ax + (size_t)(m0 + lrow) * (size_t)K
                                     : Bw + (size_t)(n0 + lrow) * (size_t)K;
    const uint32_t sm_row = (uint32_t)lmat * MAT + (uint32_t)lrow * ROWB;

    auto load_stage = [&](int slot, int c) {
        const uint32_t d = sb + (uint32_t)slot * STAGE + sm_row;
        const __half* g = gsrc + (size_t)c * BK;
#pragma unroll
        for (int q = 0; q < 4; ++q)
            cp16(d + q * 16u, g + q * 8);
    };

    const int r15  = l & 15;
    const int half = l >> 4;

    auto load_frags = [&](Frags& f, uint32_t stageb, int step) {
        const uint32_t koff = (uint32_t)(step * 2 + half) * 16u;
#pragma unroll
        for (int i = 0; i < 4; ++i) {
            uint32_t ad = stageb + (uint32_t)(wm0 + i * 16 + r15) * ROWB + koff;
            ldm4(f.A[i], ad + OFF_A);
        }
#pragma unroll
        for (int p = 0; p < 2; ++p) {
            uint32_t bd = stageb + (uint32_t)(wn0 + p * 16 + r15) * ROWB + koff;
            ldm4(f.B[p], bd + OFF_B);
        }
    };

    float acc[4][4][4];
#pragma unroll
    for (int i = 0; i < 4; ++i)
#pragma unroll
        for (int j = 0; j < 4; ++j)
#pragma unroll
            for (int k = 0; k < 4; ++k) acc[i][j][k] = 0.0f;

    auto mma_frags = [&](const Frags& f) {
        // 16 independent MMAs -> accumulator reuse distance 16
#pragma unroll
        for (int i = 0; i < 4; ++i)
#pragma unroll
            for (int j = 0; j < 4; ++j) {
                int p = j >> 1, t = j & 1;
                mma16816(acc[i][j], f.A[i], f.B[p][t], f.B[p][t + 2]);
            }
    };

    const int nch = K / BK;

    // ---- prologue: fill stages 0,1; prefetch first fragment set ----
    load_stage(0, 0);
    cp_commit();
    load_stage(1, 1);
    cp_commit();
    asm volatile("cp.async.wait_group 1;");   // chunk 0 resident
    __syncthreads();

    Frags f0, f1;
    load_frags(f0, sb, 0);                     // chunk 0, step 0

    // ---- mainloop (R8 schedule) ----
    int slot = 0;
#pragma unroll 1
    for (int c = 0; c < nch; ++c) {
        const uint32_t stc = sb + (uint32_t)slot * STAGE;
        const int slot2 = (slot + 2 >= STAGES) ? slot + 2 - STAGES : slot + 2;
        const int slot1 = (slot + 1 >= STAGES) ? slot + 1 - STAGES : slot + 1;

        // prefetch step-1 fragments of this chunk (same stage, already visible)
        load_frags(f1, stc, 1);

        // 16 MMAs on step-0 fragments (loaded last iteration)
        mma_frags(f0);

        // refill ring: chunk c+2 -> slot2
        if (c + 2 < nch) load_stage(slot2, c + 2);
        cp_commit();
        asm volatile("cp.async.wait_group 1;");// all but newest retired -> chunk c+1 done
        __syncthreads();                       // cross-warp visibility of stage c+1

        // prefetch step-0 fragments of chunk c+1
        if (c + 1 < nch) load_frags(f0, sb + (uint32_t)slot1 * STAGE, 0);

        // 16 MMAs on step-1 fragments
        mma_frags(f1);

        slot = slot1;
    }

    // ---- epilogue ----
    const int er = l >> 2;
    const int ec = (l & 3) * 2;
#pragma unroll
    for (int i = 0; i < 4; ++i)
#pragma unroll
        for (int j = 0; j < 4; ++j) {
            int n = n0 + wn0 + j * 8 + ec;
            float bb0 = bias[n], bb1 = bias[n + 1];
#pragma unroll
            for (int h = 0; h < 2; ++h) {
                int m = m0 + wm0 + i * 16 + er + h * 8;
                float v0 = acc[i][j][2 * h]     + bb0;
                float v1 = acc[i][j][2 * h + 1] + bb1;
                if (MODE == 1) {
                    v0 = 0.5f * v0 * (1.0f + erff(v0 * 0.70710678118654752f));
                    v1 = 0.5f * v1 * (1.0f + erff(v1 * 0.70710678118654752f));
                    __half2 hv = __floats2half2_rn(v0, v1);
                    *(uint32_t*)(outH + (size_t)m * EMBED + n) = *(uint32_t*)&hv;
                } else {
                    float2 o; o.x = v0; o.y = v1;
                    *(float2*)(out + (size_t)m * EMBED + n) = o;
                }
            }
        }
}

// ---------------- harness entry ----------------
extern "C" void kernel_launch(void* const* d_in, const int* in_sizes, int n_in,
                              void* d_out, int out_size) {
    const int*   idxs = (const int*)d_in[0];
    const float* tok  = (const float*)d_in[1];
    const float* W1   = (const float*)d_in[2];
    const float* b1   = (const float*)d_in[3];
    const float* W2   = (const float*)d_in[4];
    const float* b2   = (const float*)d_in[5];
    float* out = (float*)d_out;

    void *w1h, *w2h, *a, *y;
    cudaGetSymbolAddress(&w1h, g_W1h);
    cudaGetSymbolAddress(&w2h, g_W2h);
    cudaGetSymbolAddress(&a,   g_A);
    cudaGetSymbolAddress(&y,   g_Y);

    cudaFuncSetAttribute(gemm_mma<1>,
                         cudaFuncAttributeMaxDynamicSharedMemorySize, SMEM_TOTAL);
    cudaFuncSetAttribute(gemm_mma<0>,
                         cudaFuncAttributeMaxDynamicSharedMemorySize, SMEM_TOTAL);

    const int nW = EMBED * FRONT;
    convert_weights<<<(nW + 255) / 256, 256>>>(W1, W2);
    gather_fp16<<<TOKENS, 256>>>(tok, idxs);

    // GEMM1: A @ W1^T + b1, GELU -> Y fp16
    gemm_mma<1><<<dim3(EMBED / BN, TOKENS / BM), THREADS, SMEM_TOTAL>>>(
        (const __half*)a, (const __half*)w1h, b1, nullptr, (__half*)y, FRONT);

    // GEMM2: Y @ W2^T + b2 -> out fp32
    gemm_mma<0><<<dim3(EMBED / BN, TOKENS / BM), THREADS, SMEM_TOTAL>>>(
        (const __half*)y, (const __half*)w2h, b2, out, nullptr, EMBED);
}

// round 13
// speedup vs baseline: 4.1676x; 1.5652x over previous
#include <cuda_runtime.h>
#include <cuda_fp16.h>
#include <cstdint>

#define FRONT 3072
#define EMBED 768
#define TOKENS 16384

// ---------------- device scratch (no dynamic alloc allowed) ----------------
__device__ __half g_W1h[EMBED * FRONT];                 // fp16 weights
__device__ __half g_W2h[EMBED * EMBED];
__device__ __half g_A[(size_t)TOKENS * FRONT];          // gathered embed, fp16
__device__ __half g_Y[(size_t)TOKENS * EMBED];          // GELU(h1), fp16

// ---------------- tiling ----------------
constexpr int BM = 128;
constexpr int BN = 256;
constexpr int BK = 32;              // fp16 K columns per stage (2 k16 steps)
constexpr int THREADS = 256;
constexpr int STAGES = 3;

// 80-byte pitch = 5 x 16B units (odd) -> any 8 consecutive rows at a fixed 16B
// chunk column hit 8 distinct bank groups: ldmatrix conflict-free, NO swizzle.
constexpr int ROWB   = 80;
constexpr int SROWS  = BM + BN;             // 384 rows per stage (A then B)
constexpr int STAGE  = SROWS * ROWB;        // 30720 B
constexpr int SMEM_TOTAL = STAGES * STAGE;  // 92160 B -> 1 CTA/SM
constexpr int OFF_A = 0;
constexpr int OFF_B = BM * ROWB;            // B rows start at row 128

// ---------------- PTX helpers (plain compute_103-legal) ----------------
__device__ __forceinline__ uint32_t smem_u32(const void* p) {
    uint32_t a;
    asm("{ .reg .u64 t; cvta.to.shared.u64 t, %1; cvt.u32.u64 %0, t; }" : "=r"(a) : "l"(p));
    return a;
}
__device__ __forceinline__ void cp16(uint32_t s, const void* g) {
    asm volatile("cp.async.cg.shared.global [%0], [%1], 16;" :: "r"(s), "l"(g));
}
__device__ __forceinline__ void cp_commit() {
    asm volatile("cp.async.commit_group;");
}
__device__ __forceinline__ void ldm4(uint32_t r[4], uint32_t a) {
    asm volatile("ldmatrix.sync.aligned.m8n8.x4.shared.b16 {%0,%1,%2,%3}, [%4];"
                 : "=r"(r[0]), "=r"(r[1]), "=r"(r[2]), "=r"(r[3]) : "r"(a));
}
__device__ __forceinline__ void mma16816(float c[4], const uint32_t a[4],
                                         uint32_t b0, uint32_t b1) {
    asm volatile(
        "mma.sync.aligned.m16n8k16.row.col.f32.f16.f16.f32 "
        "{%0,%1,%2,%3}, {%4,%5,%6,%7}, {%8,%9}, {%0,%1,%2,%3};"
        : "+f"(c[0]), "+f"(c[1]), "+f"(c[2]), "+f"(c[3])
        : "r"(a[0]), "r"(a[1]), "r"(a[2]), "r"(a[3]), "r"(b0), "r"(b1));
}

// ---------------- prep: weights fp32 -> fp16 ----------------
__global__ void convert_weights(const float* __restrict__ W1, const float* __restrict__ W2) {
    int i = blockIdx.x * blockDim.x + threadIdx.x;
    if (i < EMBED * FRONT) g_W1h[i] = __float2half_rn(W1[i]);
    if (i < EMBED * EMBED) g_W2h[i] = __float2half_rn(W2[i]);
}

// ---------------- prep: gather + fp16 convert of embedding rows ----------------
__global__ void __launch_bounds__(256, 4)
gather_fp16(const float* __restrict__ tok, const int* __restrict__ idxs) {
    const int row = blockIdx.x;
    const float4* src = (const float4*)(tok + (size_t)idxs[row] * FRONT);
    uint2* dst = (uint2*)(g_A + (size_t)row * FRONT);
#pragma unroll
    for (int t = 0; t < FRONT / 4 / 256; ++t) {
        int i = t * 256 + threadIdx.x;
        float4 v = src[i];
        __half2 h01 = __floats2half2_rn(v.x, v.y);
        __half2 h23 = __floats2half2_rn(v.z, v.w);
        uint2 o;
        o.x = *(uint32_t*)&h01;
        o.y = *(uint32_t*)&h23;
        dst[i] = o;
    }
}

// ---------------- fragment set for one k16-step (warp tile 64x64) ----------------
struct Frags {
    uint32_t A[4][4], B[4][4];
};

// ---------------- single fp16 mma.sync GEMM, warp 64x64, ping-pong ----------------
// acc = sum_k A[m,k] * B[n,k]     (fp16 in, fp32 accum)
// MODE 0: out fp32 = acc + bias
// MODE 1: v = gelu(acc + bias); write fp16 to outH
template <int MODE>
__global__ void __launch_bounds__(THREADS, 1)
gemm_mma(const __half* __restrict__ Ax,
         const __half* __restrict__ Bw,
         const float* __restrict__ bias,
         float* __restrict__ out,
         __half* __restrict__ outH,
         int K) {
    extern __shared__ char sm[];
    const uint32_t sb = smem_u32(sm);

    const int tid = threadIdx.x;
    const int wid = tid >> 5;
    const int l   = tid & 31;
    const int m0  = blockIdx.y * BM;
    const int n0  = blockIdx.x * BN;
    const int wm0 = (wid >> 2) * 64;   // 2 warps over M
    const int wn0 = (wid & 3) * 64;    // 4 warps over N

    // ---- stage loader: 384 rows x 4 chunks = 1536 cp16, 6 per thread ----
    const __half* gptr[6];
    uint32_t      soff[6];
#pragma unroll
    for (int x = 0; x < 6; ++x) {
        int id  = tid + x * THREADS;     // 0..1535
        int row = id >> 2;               // 0..383
        int q   = id & 3;                // 16B chunk in row
        gptr[x] = ((row < BM) ? Ax + (size_t)(m0 + row) * (size_t)K
                              : Bw + (size_t)(n0 + row - BM) * (size_t)K) + q * 8;
        soff[x] = (uint32_t)row * ROWB + (uint32_t)q * 16u;
    }

    auto load_stage = [&](int slot, int c) {
        const uint32_t d = sb + (uint32_t)slot * STAGE;
        const size_t go = (size_t)c * BK;
#pragma unroll
        for (int x = 0; x < 6; ++x)
            cp16(d + soff[x], gptr[x] + go);
    };

    const int r15  = l & 15;
    const int half = l >> 4;

    auto load_frags = [&](Frags& f, uint32_t stageb, int step) {
        const uint32_t koff = (uint32_t)(step * 2 + half) * 16u;
#pragma unroll
        for (int i = 0; i < 4; ++i) {
            uint32_t ad = stageb + OFF_A + (uint32_t)(wm0 + i * 16 + r15) * ROWB + koff;
            ldm4(f.A[i], ad);
        }
#pragma unroll
        for (int p = 0; p < 4; ++p) {
            uint32_t bd = stageb + OFF_B + (uint32_t)(wn0 + p * 16 + r15) * ROWB + koff;
            ldm4(f.B[p], bd);
        }
    };

    float acc[4][8][4];
#pragma unroll
    for (int i = 0; i < 4; ++i)
#pragma unroll
        for (int j = 0; j < 8; ++j)
#pragma unroll
            for (int k = 0; k < 4; ++k) acc[i][j][k] = 0.0f;

    auto mma_frags = [&](const Frags& f) {
        // 32 independent MMAs per step
#pragma unroll
        for (int i = 0; i < 4; ++i)
#pragma unroll
            for (int j = 0; j < 8; ++j) {
                int p = j >> 1, t = j & 1;
                mma16816(acc[i][j], f.A[i], f.B[p][t], f.B[p][t + 2]);
            }
    };

    const int nch = K / BK;

    // ---- prologue: fill stages 0,1; prefetch first fragment set ----
    load_stage(0, 0);
    cp_commit();
    load_stage(1, 1);
    cp_commit();
    asm volatile("cp.async.wait_group 1;");   // chunk 0 resident
    __syncthreads();

    Frags f0, f1;
    load_frags(f0, sb, 0);                     // chunk 0, step 0

    // ---- mainloop (proven R8 depth-2 schedule) ----
    int slot = 0;
#pragma unroll 1
    for (int c = 0; c < nch; ++c) {
        const uint32_t stc = sb + (uint32_t)slot * STAGE;
        const int slot2 = (slot + 2 >= STAGES) ? slot + 2 - STAGES : slot + 2;
        const int slot1 = (slot + 1 >= STAGES) ? slot + 1 - STAGES : slot + 1;

        // prefetch step-1 fragments of this chunk (same stage, already visible)
        load_frags(f1, stc, 1);

        // 32 MMAs on step-0 fragments (loaded last iteration)
        mma_frags(f0);

        // refill ring: chunk c+2 -> slot2
        if (c + 2 < nch) load_stage(slot2, c + 2);
        cp_commit();
        asm volatile("cp.async.wait_group 1;");// all but newest retired -> chunk c+1 done
        __syncthreads();                       // cross-warp visibility of stage c+1

        // prefetch step-0 fragments of chunk c+1
        if (c + 1 < nch) load_frags(f0, sb + (uint32_t)slot1 * STAGE, 0);

        // 32 MMAs on step-1 fragments
        mma_frags(f1);

        slot = slot1;
    }

    // ---- epilogue ----
    const int er = l >> 2;
    const int ec = (l & 3) * 2;
#pragma unroll
    for (int i = 0; i < 4; ++i)
#pragma unroll
        for (int j = 0; j < 8; ++j) {
            int n = n0 + wn0 + j * 8 + ec;
            float bb0 = bias[n], bb1 = bias[n + 1];
#pragma unroll
            for (int h = 0; h < 2; ++h) {
                int m = m0 + wm0 + i * 16 + er + h * 8;
                float v0 = acc[i][j][2 * h]     + bb0;
                float v1 = acc[i][j][2 * h + 1] + bb1;
                if (MODE == 1) {
                    v0 = 0.5f * v0 * (1.0f + erff(v0 * 0.70710678118654752f));
                    v1 = 0.5f * v1 * (1.0f + erff(v1 * 0.70710678118654752f));
                    __half2 hv = __floats2half2_rn(v0, v1);
                    *(uint32_t*)(outH + (size_t)m * EMBED + n) = *(uint32_t*)&hv;
                } else {
                    float2 o; o.x = v0; o.y = v1;
                    *(float2*)(out + (size_t)m * EMBED + n) = o;
                }
            }
        }
}

// ---------------- harness entry ----------------
extern "C" void kernel_launch(void* const* d_in, const int* in_sizes, int n_in,
                              void* d_out, int out_size) {
    const int*   idxs = (const int*)d_in[0];
    const float* tok  = (const float*)d_in[1];
    const float* W1   = (const float*)d_in[2];
    const float* b1   = (const float*)d_in[3];
    const float* W2   = (const float*)d_in[4];
    const float* b2   = (const float*)d_in[5];
    float* out = (float*)d_out;

    void *w1h, *w2h, *a, *y;
    cudaGetSymbolAddress(&w1h, g_W1h);
    cudaGetSymbolAddress(&w2h, g_W2h);
    cudaGetSymbolAddress(&a,   g_A);
    cudaGetSymbolAddress(&y,   g_Y);

    cudaFuncSetAttribute(gemm_mma<1>,
                         cudaFuncAttributeMaxDynamicSharedMemorySize, SMEM_TOTAL);
    cudaFuncSetAttribute(gemm_mma<0>,
                         cudaFuncAttributeMaxDynamicSharedMemorySize, SMEM_TOTAL);

    const int nW = EMBED * FRONT;
    convert_weights<<<(nW + 255) / 256, 256>>>(W1, W2);
    gather_fp16<<<TOKENS, 256>>>(tok, idxs);

    // GEMM1: A @ W1^T + b1, GELU -> Y fp16
    gemm_mma<1><<<dim3(EMBED / BN, TOKENS / BM), THREADS, SMEM_TOTAL>>>(
        (const __half*)a, (const __half*)w1h, b1, nullptr, (__half*)y, FRONT);

    // GEMM2: Y @ W2^T + b2 -> out fp32
    gemm_mma<0><<<dim3(EMBED / BN, TOKENS / BM), THREADS, SMEM_TOTAL>>>(
        (const __half*)y, (const __half*)w2h, b2, out, nullptr, EMBED);
}